// round 15
// baseline (speedup 1.0000x reference)
#include <cuda_runtime.h>
#include <cuda_fp16.h>
#include <cstdint>
#include <math.h>

#define TB 64
#define TT 2048
#define TC 96
#define TS 256
#define NEGF (-1e30f)
#define LOG2E 1.4426950408889634f
#define LN2   0.6931471805599453f

#define NW  11             // warps; lanes 0..7 ghost, lanes 8..31 own 24 pairs
#define NTH (NW * 32)      // 352
#define GH  8              // ghost lanes = trapezoid depth
#define OWN 24             // owned pairs per warp
#define NROW 272           // rows: 0..7 pad, 8..263 = pair 0..255, 264 blank, 265..271 pad
#define PADV (-60000.0f)   // fp16 log-zero pad

// transposed table: g_gtT[b][row][t] fp16, row = pair + 8
__device__ __align__(16) __half g_gtT[(size_t)TB * NROW * TT];

__device__ __forceinline__ float ex2f_(float x) {
    float r; asm("ex2.approx.f32 %0, %1;" : "=f"(r) : "f"(x)); return r;
}
__device__ __forceinline__ float lg2f_(float x) {
    float r; asm("lg2.approx.f32 %0, %1;" : "=f"(r) : "f"(x)); return r;
}
__device__ __forceinline__ float lse2f_(float a, float b) {
    float m = fmaxf(a, b), n = fminf(a, b);
    return m + lg2f_(1.0f + ex2f_(n - m));
}
__device__ __forceinline__ float lse3f_(float a, float b, float c) {
    float s1 = fmaxf(a, b), t1 = fminf(a, b);
    float m  = fmaxf(s1, c);
    float md = fmaxf(fminf(s1, c), t1);
    float mn = fminf(t1, c);
    return m + lg2f_(1.0f + ex2f_(md - m) + ex2f_(mn - m));
}

// ---------------------------------------------------------------------------
// Gather: log-softmax + class gather -> TRANSPOSED fp16 table (t-major rows).
// Block: 256 threads, one (b, 64-t slice); grid (TT/64, TB).
// ---------------------------------------------------------------------------
__global__ void __launch_bounds__(256) gather_kernel(
    const float* __restrict__ x, const int* __restrict__ tgt32, float* out)
{
    __shared__ float raw[64][97];      // 97: de-phase banks for column reads
    __shared__ float lse2s[64];
    __shared__ int   lab[TS];

    const int tid = threadIdx.x, lane = tid & 31, wr = tid >> 5;
    const int b = blockIdx.y, t0 = blockIdx.x * 64;

    if (b == 0 && blockIdx.x == 0 && tid == 0) *out = 0.0f;

    const bool is64 = (tgt32[1] == 0);       // labels>=1 => hi word 0 iff i64 LE
    const int  stride = is64 ? 2 : 1;
    lab[tid] = tgt32[((size_t)b * TS + tid) * stride];

    const float* xr = x + ((size_t)b * TT + t0) * TC;
    for (int k = tid; k < 64 * 96; k += 256) raw[k / 96][k % 96] = xr[k];
    __syncthreads();

    #pragma unroll
    for (int rr = 0; rr < 8; ++rr) {
        int row = wr * 8 + rr;
        float v0 = raw[row][lane], v1 = raw[row][lane + 32], v2 = raw[row][lane + 64];
        float m = fmaxf(fmaxf(v0, v1), v2);
        #pragma unroll
        for (int o = 16; o; o >>= 1) m = fmaxf(m, __shfl_xor_sync(0xffffffffu, m, o));
        float s = expf(v0 - m) + expf(v1 - m) + expf(v2 - m);
        #pragma unroll
        for (int o = 16; o; o >>= 1) s += __shfl_xor_sync(0xffffffffu, s, o);
        if (lane == 0) lse2s[row] = fmaf(m, LOG2E, log2f(s));
    }
    __syncthreads();

    // each thread writes its label row: 64 t = 128 B contiguous
    {
        const int c = lab[tid];
        __half* dst = g_gtT + (size_t)(b * NROW + tid + 8) * TT + t0;
        #pragma unroll
        for (int tc = 0; tc < 64; tc += 8) {
            __half h[8];
            #pragma unroll
            for (int k = 0; k < 8; ++k)
                h[k] = __float2half(fmaf(raw[tc + k][c], LOG2E, -lse2s[tc + k]));
            *(uint4*)(dst + tc) = *(const uint4*)h;
        }
    }
    // blank row (264) + pad rows (0..7, 265..271)
    if (tid < 16) {
        int row = (tid < 8) ? tid : ((tid == 8) ? 264 : (256 + tid));
        __half* dst = g_gtT + (size_t)(b * NROW + row) * TT + t0;
        if (tid == 8) {
            #pragma unroll
            for (int tc = 0; tc < 64; tc += 8) {
                __half h[8];
                #pragma unroll
                for (int k = 0; k < 8; ++k)
                    h[k] = __float2half(fmaf(raw[tc + k][0], LOG2E, -lse2s[tc + k]));
                *(uint4*)(dst + tc) = *(const uint4*)h;
            }
        } else {
            __half h[8];
            #pragma unroll
            for (int k = 0; k < 8; ++k) h[k] = __float2half(PADV);
            uint4 pq = *(const uint4*)h;
            #pragma unroll
            for (int tc = 0; tc < 64; tc += 8) *(uint4*)(dst + tc) = pq;
        }
    }
}

// ---------------------------------------------------------------------------
// Main kernel: wavefront-blocked (D=8) alpha recursion, register-fed.
// Warp w, lane j: pair p = 24w + j - 8; j<8 = ghost lanes.
// ---------------------------------------------------------------------------
__global__ void __launch_bounds__(NTH, 1) ctc_kernel(
    const int* __restrict__ tgt32,
    const int* __restrict__ tmask,
    float*     __restrict__ out)
{
    __shared__ float bnd[2][NW][GH][2];  // [parity][warp][slot][aE,aO]
    __shared__ float fin[514];
    __shared__ int   lab[TS];
    __shared__ int   tlen_sh;

    const int tid = threadIdx.x, lane = tid & 31, w = tid >> 5;
    const int b = blockIdx.x;
    const int p = OWN * w + lane - GH;   // pair index, -8..263

    const bool is64 = (tgt32[1] == 0);
    const int  stride = is64 ? 2 : 1;
    if (tid < TS) lab[tid] = tgt32[((size_t)b * TS + tid) * stride];
    ((float*)bnd)[tid] = NEGF;           // 2*11*8*2 = 352 = NTH exactly
    if (w == 0) {
        int s = 0;
        #pragma unroll
        for (int k = lane; k < TS; k += 32) s += tmask[b * TS + k];
        #pragma unroll
        for (int o = 16; o; o >>= 1) s += __shfl_xor_sync(0xffffffffu, s, o);
        if (lane == 0) tlen_sh = s;
    }
    __syncthreads();

    const bool skip = (p > 0) && (p < 256) && (lab[p] != lab[p - 1]);

    const __half* rowp = g_gtT + (size_t)(b * NROW + p + 8) * TT;
    const __half* blkp = g_gtT + (size_t)(b * NROW + 264) * TT;

    // 2-round register double buffer
    uint4 lqA = *(const uint4*)(rowp);      uint4 bqA = *(const uint4*)(blkp);
    uint4 lqB = *(const uint4*)(rowp + 8);  uint4 bqB = *(const uint4*)(blkp + 8);

    // virtual t=-1 seed: aE(p=0)=0 makes the uniform loop emit alpha0 at t=0
    float aE = (p == 0) ? 0.0f : NEGF;
    float aO = NEGF;
    int   pb = 0;

    #pragma unroll 2
    for (int r = 0; r < TT / 8; ++r) {
        __syncthreads();
        if (lane < GH && w > 0) {
            aE = bnd[pb][w - 1][lane][0];
            aO = bnd[pb][w - 1][lane][1];
        }

        uint4 lq = (r & 1) ? lqB : lqA;
        uint4 bq = (r & 1) ? bqB : bqA;
        if (r + 2 < TT / 8) {
            if (r & 1) { lqB = *(const uint4*)(rowp + (r + 2) * 8);
                         bqB = *(const uint4*)(blkp + (r + 2) * 8); }
            else       { lqA = *(const uint4*)(rowp + (r + 2) * 8);
                         bqA = *(const uint4*)(blkp + (r + 2) * 8); }
        }
        const __half* lh = (const __half*)&lq;
        const __half* bh = (const __half*)&bq;

        #pragma unroll
        for (int k = 0; k < 8; ++k) {
            float lp  = __half2float(lh[k]);
            float lpB = __half2float(bh[k]);
            float lo = __shfl_up_sync(0xffffffffu, aO, 1);
            if (lane == 0) lo = NEGF;
            float nE = lse2f_(aE, lo) + lpB;                   // state 2p
            float nO = lse3f_(aO, aE, skip ? lo : NEGF) + lp;  // state 2p+1
            aE = nE; aO = nO;
        }

        if (lane >= 32 - GH) {
            bnd[pb ^ 1][w][lane - (32 - GH)][0] = aE;
            bnd[pb ^ 1][w][lane - (32 - GH)][1] = aO;
        }
        pb ^= 1;
    }

    if (lane >= GH && p <= 256) {
        fin[2 * p] = aE;
        if (p < 256) fin[2 * p + 1] = aO;
    }
    __syncthreads();

    if (tid == 0) {
        int len = tlen_sh;
        float loss = 0.0f;
        if (len >= 1 && len <= TS) {
            float la = lse2f_(fin[2 * len], fin[2 * len - 1]);
            float l  = -la * LN2;
            if (isfinite(l) && l < 1e29f)
                loss = l / ((float)len * (float)TB);
        }
        atomicAdd(out, loss);
    }
}

// ---------------------------------------------------------------------------
extern "C" void kernel_launch(void* const* d_in, const int* in_sizes, int n_in,
                              void* d_out, int out_size) {
    const float* x     = (const float*)d_in[0];   // predictions [B,T,C] f32
    const int*   tgt   = (const int*)  d_in[1];   // targets (int32 or int64 words)
    const int*   tmask = (const int*)  d_in[3];   // targets_mask [B,S] i32
    float* out = (float*)d_out;

    dim3 ggrid(TT / 64, TB);
    gather_kernel<<<ggrid, 256>>>(x, tgt, out);
    ctc_kernel<<<TB, NTH>>>(tgt, tmask, out);
}

// round 16
// speedup vs baseline: 1.2136x; 1.2136x over previous
#include <cuda_runtime.h>
#include <cuda_fp16.h>
#include <cstdint>
#include <math.h>

#define TB 64
#define TT 2048
#define TC 96
#define TS 256
#define NEGF (-1e30f)
#define LOG2E 1.4426950408889634f
#define LN2   0.6931471805599453f

#define NW  11             // warps; lanes 0..7 ghost, lanes 8..31 own 24 pairs
#define NTH (NW * 32)      // 352
#define GH  8              // ghost lanes = trapezoid depth (steps/round)
#define OWN 24             // owned pairs per warp
#define GROW 272           // half2 entries per row (idx = pair+8; 0..7,264..271 pad)
#define RCH 4              // ring chunks of 8 rows (4*8*1088 B = 34816 B)
#define NCHK (TT / 8)
#define PADH (-60000.0f)   // fp16 log-zero pad

// G2[b][t][e] = half2(lp_label(e-8), lp_blank), e in [0,272)
__device__ __align__(16) __half2 g_gt2[(size_t)TB * TT * GROW];

__device__ __forceinline__ float ex2f_(float x) {
    float r; asm("ex2.approx.f32 %0, %1;" : "=f"(r) : "f"(x)); return r;
}
__device__ __forceinline__ float lg2f_(float x) {
    float r; asm("lg2.approx.f32 %0, %1;" : "=f"(r) : "f"(x)); return r;
}
__device__ __forceinline__ float lse2f_(float a, float b) {
    float m = fmaxf(a, b), n = fminf(a, b);
    return m + lg2f_(1.0f + ex2f_(n - m));
}
__device__ __forceinline__ float lse3f_(float a, float b, float c) {
    float s1 = fmaxf(a, b), t1 = fminf(a, b);
    float m  = fmaxf(s1, c);
    float md = fmaxf(fminf(s1, c), t1);
    float mn = fminf(t1, c);
    return m + lg2f_(1.0f + ex2f_(md - m) + ex2f_(mn - m));
}

// ---------------------------------------------------------------------------
// Gather: precise log-softmax + class gather -> half2 (label, blank) table.
// 256 threads = 8 warps, one warp per t-row; grid (TT/8, TB).
// ---------------------------------------------------------------------------
__global__ void __launch_bounds__(256) gather_kernel(
    const float* __restrict__ x, const int* __restrict__ tgt32, float* out)
{
    __shared__ int   lab[TS];
    __shared__ float raw[8][TC];

    const int tid = threadIdx.x, lane = tid & 31, r = tid >> 5;
    const int b = blockIdx.y, t0 = blockIdx.x * 8;

    if (b == 0 && blockIdx.x == 0 && tid == 0) *out = 0.0f;

    const bool is64 = (tgt32[1] == 0);       // labels>=1 => hi word 0 iff i64 LE
    const int  stride = is64 ? 2 : 1;
    lab[tid] = tgt32[((size_t)b * TS + tid) * stride];

    const float* xr = x + ((size_t)b * TT + t0 + r) * TC;
    float v0 = xr[lane], v1 = xr[lane + 32], v2 = xr[lane + 64];
    raw[r][lane] = v0; raw[r][lane + 32] = v1; raw[r][lane + 64] = v2;
    float m = fmaxf(fmaxf(v0, v1), v2);
    #pragma unroll
    for (int o = 16; o; o >>= 1) m = fmaxf(m, __shfl_xor_sync(0xffffffffu, m, o));
    float s = expf(v0 - m) + expf(v1 - m) + expf(v2 - m);
    #pragma unroll
    for (int o = 16; o; o >>= 1) s += __shfl_xor_sync(0xffffffffu, s, o);
    float lse2 = fmaf(m, LOG2E, log2f(s));
    __syncthreads();

    __half2* Gr = g_gt2 + ((size_t)b * TT + t0 + r) * GROW;
    float lpB = fmaf(raw[r][0], LOG2E, -lse2);
    __half hB = __float2half(lpB);
    __half hP = __float2half(PADH);
    #pragma unroll
    for (int j = lane; j < GROW; j += 32) {
        __half hl = hP;
        if (j >= 8 && j < 264)
            hl = __float2half(fmaf(raw[r][lab[j - 8]], LOG2E, -lse2));
        Gr[j] = __halves2half2(hl, hB);
    }
}

// ---------------------------------------------------------------------------
// Main kernel: wavefront-blocked (D=8) alpha recursion, register-double-
// buffered half2 feed through a cp.async ring. 1 barrier per 8 timesteps.
// Warp w, lane j: pair p = 24w + j - 8; lanes j<8 = ghosts.
// ---------------------------------------------------------------------------
__global__ void __launch_bounds__(NTH, 1) ctc_kernel(
    const int* __restrict__ tgt32,
    const int* __restrict__ tmask,
    float*     __restrict__ out)
{
    __shared__ __align__(16) __half2 ring[RCH][8 * GROW];  // 34816 B
    __shared__ float bnd[2][NW][GH][2];  // [parity][warp][slot][aE,aO]
    __shared__ float fin[514];
    __shared__ int   lab[TS];
    __shared__ int   tlen_sh;

    const int tid = threadIdx.x, lane = tid & 31, w = tid >> 5;
    const int b = blockIdx.x;
    const int p = OWN * w + lane - GH;   // pair index, -8..263
    const int idx = p + 8;               // table entry, 0..271

    const bool is64 = (tgt32[1] == 0);
    const int  stride = is64 ? 2 : 1;
    if (tid < TS) lab[tid] = tgt32[((size_t)b * TS + tid) * stride];
    ((float*)bnd)[tid] = NEGF;           // 2*11*8*2 = 352 = NTH exactly
    if (w == 0) {
        int s = 0;
        #pragma unroll
        for (int k = lane; k < TS; k += 32) s += tmask[b * TS + k];
        #pragma unroll
        for (int o = 16; o; o >>= 1) s += __shfl_xor_sync(0xffffffffu, s, o);
        if (lane == 0) tlen_sh = s;
    }
    __syncthreads();

    const bool skip = (p > 0) && (p < 256) && (lab[p] != lab[p - 1]);

    const __half2* Gb = g_gt2 + ((size_t)b * TT) * GROW;

    // one chunk = 8 rows = 544 x 16 B contiguous
    auto issue_chunk = [&](int c) {
        if (c < NCHK) {
            unsigned sa = (unsigned)__cvta_generic_to_shared(ring[c % RCH]);
            const __half2* src = Gb + (size_t)c * (8 * GROW);
            #pragma unroll
            for (int k = tid; k < 544; k += NTH)
                asm volatile("cp.async.ca.shared.global [%0], [%1], 16;"
                             :: "r"(sa + k * 16), "l"(src + k * 4));
        }
        asm volatile("cp.async.commit_group;");
    };

    issue_chunk(0); issue_chunk(1); issue_chunk(2);
    asm volatile("cp.async.wait_group 2;");   // chunk 0 resident
    __syncthreads();

    // preload round 0's 8 entries into registers
    unsigned cur[8], nxt[8];
    {
        const __half2* s0 = ring[0];
        #pragma unroll
        for (int k = 0; k < 8; ++k)
            cur[k] = *(const unsigned*)(s0 + k * GROW + idx);
    }

    // virtual t=-1 seed: aE(p=0)=0 makes the uniform loop emit alpha0 at t=0
    float aE = (p == 0) ? 0.0f : NEGF;
    float aO = NEGF;
    int   pb = 0;

    #pragma unroll 2
    for (int r = 0; r < TT / 8; ++r) {
        issue_chunk(r + 3);
        asm volatile("cp.async.wait_group 2;");   // chunk r+1 resident
        __syncthreads();

        // ghost refresh from left warp's last-round publish
        if (lane < GH && w > 0) {
            aE = bnd[pb][w - 1][lane][0];
            aO = bnd[pb][w - 1][lane][1];
        }

        // prefetch round r+1's entries (slot already resident)
        {
            const __half2* sn = ring[(r + 1) % RCH];
            #pragma unroll
            for (int k = 0; k < 8; ++k)
                nxt[k] = *(const unsigned*)(sn + k * GROW + idx);
        }

        #pragma unroll
        for (int k = 0; k < 8; ++k) {
            float2 lp2 = __half22float2(*(const __half2*)&cur[k]); // x=lab, y=blank
            float lo = __shfl_up_sync(0xffffffffu, aO, 1);
            if (lane == 0) lo = NEGF;
            float nE = lse2f_(aE, lo) + lp2.y;                    // state 2p
            float nO = lse3f_(aO, aE, skip ? lo : NEGF) + lp2.x;  // state 2p+1
            aE = nE; aO = nO;
        }

        if (lane >= 32 - GH) {       // publish top GH owned pairs for warp w+1
            bnd[pb ^ 1][w][lane - (32 - GH)][0] = aE;
            bnd[pb ^ 1][w][lane - (32 - GH)][1] = aO;
        }
        pb ^= 1;

        #pragma unroll
        for (int k = 0; k < 8; ++k) cur[k] = nxt[k];
    }

    if (lane >= GH && p <= 256) {    // owned, in-trellis
        fin[2 * p] = aE;
        if (p < 256) fin[2 * p + 1] = aO;
    }
    __syncthreads();

    if (tid == 0) {
        int len = tlen_sh;
        float loss = 0.0f;
        if (len >= 1 && len <= TS) {
            float la = lse2f_(fin[2 * len], fin[2 * len - 1]);
            float l  = -la * LN2;
            if (isfinite(l) && l < 1e29f)
                loss = l / ((float)len * (float)TB);
        }
        atomicAdd(out, loss);
    }
}

// ---------------------------------------------------------------------------
extern "C" void kernel_launch(void* const* d_in, const int* in_sizes, int n_in,
                              void* d_out, int out_size) {
    const float* x     = (const float*)d_in[0];   // predictions [B,T,C] f32
    const int*   tgt   = (const int*)  d_in[1];   // targets (int32 or int64 words)
    const int*   tmask = (const int*)  d_in[3];   // targets_mask [B,S] i32
    float* out = (float*)d_out;

    dim3 ggrid(TT / 8, TB);
    gather_kernel<<<ggrid, 256>>>(x, tgt, out);
    ctc_kernel<<<TB, NTH>>>(tgt, tmask, out);
}